// round 13
// baseline (speedup 1.0000x reference)
#include <cuda_runtime.h>
#include <cuda_bf16.h>
#include <stdint.h>

#define RR 3
#define NN 50000
#define EE 1000000
#define BB 2048
#define INP 256
#define HID 512
#define OUTD 256

#define SLD 40   // smem K-stride (elements): 20r+c hits all 32 banks distinctly

// ---------------- static scratch (no allocations allowed) ----------------
__device__ int g_bn[BB];
__device__ unsigned char g_inb[NN];
__device__ unsigned char g_app[RR][NN];
__device__ unsigned char g_src[RR][BB];     // row is an edge source (renumbered)
__device__ int g_newid[RR][NN];
__device__ int g_cnt[RR];
__device__ int g_ks[RR][EE];
__device__ int g_kd[RR][EE];
__device__ __align__(16) float g_deg[RR][BB];
__device__ __align__(16) float g_xw1[(size_t)RR * BB * HID];
__device__ __align__(16) float g_h[(size_t)RR * BB * HID];
__device__ __align__(16) float g_xw2[(size_t)RR * BB * OUTD];
__device__ __align__(16) float g_bnsum[RR][HID];
__device__ __align__(16) float g_bnsq[RR][HID];

// ---------------- helpers ----------------
__device__ __forceinline__ int detect64(const void* bn) {
    long long v = ((const long long*)bn)[0];   // sorted distinct ids: int32 view gives >= 2^32
    return (v >= 0 && v < NN) ? 1 : 0;
}

__device__ __forceinline__ void mma16816(float* c, const uint32_t* a, const uint32_t* b) {
    asm volatile(
        "mma.sync.aligned.m16n8k16.row.col.f32.bf16.bf16.f32 "
        "{%0,%1,%2,%3}, {%4,%5,%6,%7}, {%8,%9}, {%0,%1,%2,%3};"
        : "+f"(c[0]), "+f"(c[1]), "+f"(c[2]), "+f"(c[3])
        : "r"(a[0]), "r"(a[1]), "r"(a[2]), "r"(a[3]), "r"(b[0]), "r"(b[1]));
}

// split fp32x4 -> bf16 hi (truncate) + bf16 lo (rn of residual); 8B-aligned stores
__device__ __forceinline__ void split_store4(__nv_bfloat16* ph, __nv_bfloat16* pl, float4 v) {
    uint32_t b0 = __float_as_uint(v.x), b1 = __float_as_uint(v.y);
    uint32_t b2 = __float_as_uint(v.z), b3 = __float_as_uint(v.w);
    uint2 H;
    H.x = (b0 >> 16) | (b1 & 0xFFFF0000u);
    H.y = (b2 >> 16) | (b3 & 0xFFFF0000u);
    float l0 = v.x - __uint_as_float(b0 & 0xFFFF0000u);
    float l1 = v.y - __uint_as_float(b1 & 0xFFFF0000u);
    float l2 = v.z - __uint_as_float(b2 & 0xFFFF0000u);
    float l3 = v.w - __uint_as_float(b3 & 0xFFFF0000u);
    uint2 L;
    asm("cvt.rn.bf16x2.f32 %0, %1, %2;" : "=r"(L.x) : "f"(l1), "f"(l0));
    asm("cvt.rn.bf16x2.f32 %0, %1, %2;" : "=r"(L.y) : "f"(l3), "f"(l2));
    *(uint2*)ph = H;
    *(uint2*)pl = L;
}
__device__ __forceinline__ void split_store1(__nv_bfloat16* ph, __nv_bfloat16* pl, float v) {
    uint32_t b = __float_as_uint(v);
    *(uint16_t*)ph = (uint16_t)(b >> 16);
    float lo = v - __uint_as_float(b & 0xFFFF0000u);
    uint32_t lb;
    asm("cvt.rn.bf16x2.f32 %0, %1, %2;" : "=r"(lb) : "f"(0.f), "f"(lo));
    *(uint16_t*)pl = (uint16_t)lb;
}

// ---------------- prep: reset replay state + convert batch ids + membership ----------------
__global__ void k_prep(const void* __restrict__ bn) {
    int i = blockIdx.x * blockDim.x + threadIdx.x;   // 16384 threads
    for (int j = i; j < (RR * NN) / 4; j += 16384) ((int*)g_app)[j] = 0;
    if (i < (RR * BB) / 4) ((int*)g_src)[i] = 0;
    if (i < RR) g_cnt[i] = 0;
    if (i < RR * HID) { ((float*)g_bnsum)[i] = 0.f; ((float*)g_bnsq)[i] = 0.f; }
    if (i < BB) {
        int is64 = detect64(bn);
        int v = is64 ? (int)((const long long*)bn)[i] : ((const int*)bn)[i];
        g_bn[i] = v;
        g_inb[v] = 1;
    }
}

// ---------------- mask + compact kept edges (4 edges/thread) ----------------
__global__ void k_mask(const void* __restrict__ ei, const void* __restrict__ bn) {
    int r = blockIdx.y;
    int e0 = (blockIdx.x * blockDim.x + threadIdx.x) * 4;
    if (e0 >= EE) return;
    int is64 = detect64(bn);
    int s[4], d[4];
    if (is64) {
        const long long* b = (const long long*)ei + (size_t)r * 2 * EE;
        longlong2 s01 = *(const longlong2*)(b + e0);
        longlong2 s23 = *(const longlong2*)(b + e0 + 2);
        longlong2 d01 = *(const longlong2*)(b + EE + e0);
        longlong2 d23 = *(const longlong2*)(b + EE + e0 + 2);
        s[0] = (int)s01.x; s[1] = (int)s01.y; s[2] = (int)s23.x; s[3] = (int)s23.y;
        d[0] = (int)d01.x; d[1] = (int)d01.y; d[2] = (int)d23.x; d[3] = (int)d23.y;
    } else {
        const int* b = (const int*)ei + (size_t)r * 2 * EE;
        int4 sv = *(const int4*)(b + e0);
        int4 dv = *(const int4*)(b + EE + e0);
        s[0] = sv.x; s[1] = sv.y; s[2] = sv.z; s[3] = sv.w;
        d[0] = dv.x; d[1] = dv.y; d[2] = dv.z; d[3] = dv.w;
    }
#pragma unroll
    for (int q = 0; q < 4; q++) {
        if (g_inb[s[q]] & g_inb[d[q]]) {
            g_app[r][s[q]] = 1;
            g_app[r][d[q]] = 1;
            int j = atomicAdd(&g_cnt[r], 1);
            g_ks[r][j] = s[q];
            g_kd[r][j] = d[q];
        }
    }
}

// ---------------- scan (renumber) + map edges + smem degree histogram ----------------
__global__ void k_scanmap() {
    int r = blockIdx.x;
    int t = threadIdx.x;            // 1024 threads
    __shared__ int sh[1024];
    __shared__ float sdeg[BB];
    sdeg[t] = 1.0f;                 // self loop
    sdeg[t + 1024] = 1.0f;
    int v0 = g_bn[2 * t], v1 = g_bn[2 * t + 1];
    int a0 = g_app[r][v0], a1 = g_app[r][v1];
    int ps = a0 + a1;
    sh[t] = ps;
    __syncthreads();
    for (int off = 1; off < 1024; off <<= 1) {
        int val = (t >= off) ? sh[t - off] : 0;
        __syncthreads();
        sh[t] += val;
        __syncthreads();
    }
    int excl = sh[t] - ps;
    if (a0) g_newid[r][v0] = excl + a0 - 1;
    if (a1) g_newid[r][v1] = excl + a0 + a1 - 1;
    __syncthreads();
    int c = g_cnt[r];
    for (int j = t; j < c; j += 1024) {
        int s = g_newid[r][g_ks[r][j]];
        int d = g_newid[r][g_kd[r][j]];
        g_ks[r][j] = s;
        g_kd[r][j] = d;
        g_src[r][s] = 1;
        atomicAdd(&sdeg[d], 1.0f);
    }
    __syncthreads();
    g_deg[r][t] = sdeg[t];
    g_deg[r][t + 1024] = sdeg[t + 1024];
}

// ---------------- GEMM1 (mma.sync split-bf16): xw1 = gather(feat)@W1 ; h = dinv^2*xw1 + b1
// + per-block partial BN stats of h0.  128x128 tile, K-chunk 32, 8 warps 2(M)x4(N).
__global__ void __launch_bounds__(256) k_gemm1(
    const float* __restrict__ feat, const float* __restrict__ W1, const float* __restrict__ b1) {
    __shared__ __align__(16) __nv_bfloat16 Ah[128][SLD], Al[128][SLD];
    __shared__ __align__(16) __nv_bfloat16 Bh[128][SLD], Bl[128][SLD];
    __shared__ float sSum[128], sSq[128];
    const int z = blockIdx.z, bm = blockIdx.x, bnn = blockIdx.y;
    int tid = threadIdx.x, lane = tid & 31, wid = tid >> 5;
    int warpM = wid >> 2, warpN = wid & 3;
    int gID = lane >> 2, qID = lane & 3;
    if (tid < 128) { sSum[tid] = 0.f; sSq[tid] = 0.f; }

    float acc[4][4][4];
#pragma unroll
    for (int a = 0; a < 4; a++)
#pragma unroll
        for (int b = 0; b < 4; b++)
#pragma unroll
            for (int k = 0; k < 4; k++) acc[a][b][k] = 0.f;

    int ar = tid >> 1, ah = tid & 1;
    const float* arow = feat + ((size_t)z * NN + g_bn[bm * 128 + ar]) * INP + ah * 16;
    int nb = lane * 4, kl = wid;
    const float* wb = W1 + bnn * 128 + nb;

    for (int c = 0; c < INP / 32; c++) {
        int k0 = c * 32;
        if (c) __syncthreads();
#pragma unroll
        for (int i = 0; i < 4; i++) {
            float4 v = *(const float4*)(arow + k0 + i * 4);
            int cc = ah * 16 + i * 4;
            split_store4(&Ah[ar][cc], &Al[ar][cc], v);
        }
#pragma unroll
        for (int i = 0; i < 4; i++) {
            int k = kl + i * 8;
            float4 v = *(const float4*)(wb + (size_t)(k0 + k) * HID);
            split_store1(&Bh[nb + 0][k], &Bl[nb + 0][k], v.x);
            split_store1(&Bh[nb + 1][k], &Bl[nb + 1][k], v.y);
            split_store1(&Bh[nb + 2][k], &Bl[nb + 2][k], v.z);
            split_store1(&Bh[nb + 3][k], &Bl[nb + 3][k], v.w);
        }
        __syncthreads();
#pragma unroll
        for (int ks = 0; ks < 2; ks++) {
            int kc = ks * 16 + qID * 2;
            uint32_t fah[4][4], fal[4][4], fbh[4][2], fbl[4][2];
#pragma unroll
            for (int am = 0; am < 4; am++) {
                int r0 = warpM * 64 + am * 16 + gID;
                fah[am][0] = *(const uint32_t*)&Ah[r0][kc];
                fah[am][1] = *(const uint32_t*)&Ah[r0 + 8][kc];
                fah[am][2] = *(const uint32_t*)&Ah[r0][kc + 8];
                fah[am][3] = *(const uint32_t*)&Ah[r0 + 8][kc + 8];
                fal[am][0] = *(const uint32_t*)&Al[r0][kc];
                fal[am][1] = *(const uint32_t*)&Al[r0 + 8][kc];
                fal[am][2] = *(const uint32_t*)&Al[r0][kc + 8];
                fal[am][3] = *(const uint32_t*)&Al[r0 + 8][kc + 8];
            }
#pragma unroll
            for (int bn = 0; bn < 4; bn++) {
                int n0 = warpN * 32 + bn * 8 + gID;
                fbh[bn][0] = *(const uint32_t*)&Bh[n0][kc];
                fbh[bn][1] = *(const uint32_t*)&Bh[n0][kc + 8];
                fbl[bn][0] = *(const uint32_t*)&Bl[n0][kc];
                fbl[bn][1] = *(const uint32_t*)&Bl[n0][kc + 8];
            }
#pragma unroll
            for (int am = 0; am < 4; am++)
#pragma unroll
                for (int bn = 0; bn < 4; bn++) {
                    mma16816(acc[am][bn], fah[am], fbh[bn]);
                    mma16816(acc[am][bn], fal[am], fbh[bn]);
                    mma16816(acc[am][bn], fah[am], fbl[bn]);
                }
        }
    }
    // epilogue: write xw1 (source rows only), h, and per-column BN partials
    float csum[4][2] = {}, csq[4][2] = {};
#pragma unroll
    for (int am = 0; am < 4; am++) {
        int r0 = bm * 128 + warpM * 64 + am * 16 + gID;
        float d0 = rsqrtf(g_deg[z][r0]);
        float d1 = rsqrtf(g_deg[z][r0 + 8]);
        float s0 = d0 * d0, s1 = d1 * d1;
        int f0 = g_src[z][r0], f1 = g_src[z][r0 + 8];
#pragma unroll
        for (int bn = 0; bn < 4; bn++) {
            int cg = bnn * 128 + warpN * 32 + bn * 8 + qID * 2;
            float2 bb = *(const float2*)&b1[cg];
            size_t o0 = ((size_t)z * BB + r0) * HID + cg;
            size_t o1 = ((size_t)z * BB + r0 + 8) * HID + cg;
            float* p = acc[am][bn];
            float h00 = s0 * p[0] + bb.x, h01 = s0 * p[1] + bb.y;
            float h10 = s1 * p[2] + bb.x, h11 = s1 * p[3] + bb.y;
            if (f0) *(float2*)&g_xw1[o0] = make_float2(p[0], p[1]);
            *(float2*)&g_h[o0] = make_float2(h00, h01);
            if (f1) *(float2*)&g_xw1[o1] = make_float2(p[2], p[3]);
            *(float2*)&g_h[o1] = make_float2(h10, h11);
            csum[bn][0] += h00 + h10; csum[bn][1] += h01 + h11;
            csq[bn][0] += h00 * h00 + h10 * h10; csq[bn][1] += h01 * h01 + h11 * h11;
        }
    }
#pragma unroll
    for (int bn = 0; bn < 4; bn++) {
        int cl = warpN * 32 + bn * 8 + qID * 2;
        atomicAdd(&sSum[cl], csum[bn][0]);     atomicAdd(&sSum[cl + 1], csum[bn][1]);
        atomicAdd(&sSq[cl], csq[bn][0]);       atomicAdd(&sSq[cl + 1], csq[bn][1]);
    }
    __syncthreads();
    if (tid < 128) {
        atomicAdd(&g_bnsum[z][bnn * 128 + tid], sSum[tid]);
        atomicAdd(&g_bnsq[z][bnn * 128 + tid], sSq[tid]);
    }
}

// ---------------- edge scatter into h + telescoping BN stat corrections ----------------
// sum of ((old+a)^2 - old^2) over the atomic serialization telescopes to hfin^2 - h0^2: exact.
__global__ void k_scatter1() {
    int r = blockIdx.y;
    int c = g_cnt[r];
    int t = threadIdx.x;            // 256: cols t and t+256
    float s0 = 0.f, q0 = 0.f, s1 = 0.f, q1 = 0.f;
    for (int e = blockIdx.x; e < c; e += 128) {
        int s = g_ks[r][e], d = g_kd[r][e];
        float coeff = rsqrtf(g_deg[r][s]) * rsqrtf(g_deg[r][d]);
        const float* src = g_xw1 + ((size_t)(r * BB + s)) * HID;
        float* dst = g_h + ((size_t)(r * BB + d)) * HID;
        float a0 = coeff * src[t];
        float o0 = atomicAdd(dst + t, a0);
        s0 += a0; q0 += a0 * (2.f * o0 + a0);
        float a1 = coeff * src[t + 256];
        float o1 = atomicAdd(dst + t + 256, a1);
        s1 += a1; q1 += a1 * (2.f * o1 + a1);
    }
    if (blockIdx.x < (unsigned)c) {
        atomicAdd(&g_bnsum[r][t], s0);       atomicAdd(&g_bnsq[r][t], q0);
        atomicAdd(&g_bnsum[r][t + 256], s1); atomicAdd(&g_bnsq[r][t + 256], q1);
    }
}

// ---------------- GEMM2 (mma.sync split-bf16): xw2 = BN(h)@W2 ; out = dinv^2*xw2 + b2
// BN affine computed in-prologue from stats.  128x64 tile, 8 warps 4(M)x2(N).
__global__ void __launch_bounds__(256) k_gemm2(
    const float* __restrict__ W2, const float* __restrict__ b2,
    const float* __restrict__ gamma, const float* __restrict__ beta,
    float* __restrict__ out) {
    __shared__ __align__(16) __nv_bfloat16 Ah[128][SLD], Al[128][SLD];
    __shared__ __align__(16) __nv_bfloat16 Bh[64][SLD], Bl[64][SLD];
    __shared__ __align__(16) float sBa[HID], sBb[HID];
    const int z = blockIdx.z, bm = blockIdx.x, bnn = blockIdx.y;
    int tid = threadIdx.x, lane = tid & 31, wid = tid >> 5;
    int warpM = wid >> 1, warpN = wid & 1;
    int gID = lane >> 2, qID = lane & 3;

    // BN affine from stats (redundant per block; tiny)
    for (int i = tid; i < HID; i += 256) {
        float m = g_bnsum[z][i] * (1.0f / BB);
        float v = g_bnsq[z][i] * (1.0f / BB) - m * m;
        float istd = rsqrtf(v + 1e-5f);
        float a = gamma[i] * istd;
        sBa[i] = a;
        sBb[i] = beta[i] - m * a;
    }
    __syncthreads();

    float acc[2][4][4];
#pragma unroll
    for (int a = 0; a < 2; a++)
#pragma unroll
        for (int b = 0; b < 4; b++)
#pragma unroll
            for (int k = 0; k < 4; k++) acc[a][b][k] = 0.f;

    int ar = tid >> 1, ah = tid & 1;
    const float* arow = g_h + ((size_t)(z * BB + bm * 128 + ar)) * HID + ah * 16;
    int nb = (tid & 15) * 4, kl = tid >> 4;
    const float* wb = W2 + bnn * 64 + nb;

    for (int c = 0; c < HID / 32; c++) {
        int k0 = c * 32;
        if (c) __syncthreads();
#pragma unroll
        for (int i = 0; i < 4; i++) {
            int cc = ah * 16 + i * 4;
            float4 hv = *(const float4*)(arow + k0 + i * 4);
            float4 av = *(const float4*)&sBa[k0 + cc];
            float4 bv = *(const float4*)&sBb[k0 + cc];
            float4 v;
            v.x = hv.x * av.x + bv.x; v.y = hv.y * av.y + bv.y;
            v.z = hv.z * av.z + bv.z; v.w = hv.w * av.w + bv.w;
            split_store4(&Ah[ar][cc], &Al[ar][cc], v);
        }
#pragma unroll
        for (int i = 0; i < 2; i++) {
            int k = kl + i * 16;
            float4 v = *(const float4*)(wb + (size_t)(k0 + k) * OUTD);
            split_store1(&Bh[nb + 0][k], &Bl[nb + 0][k], v.x);
            split_store1(&Bh[nb + 1][k], &Bl[nb + 1][k], v.y);
            split_store1(&Bh[nb + 2][k], &Bl[nb + 2][k], v.z);
            split_store1(&Bh[nb + 3][k], &Bl[nb + 3][k], v.w);
        }
        __syncthreads();
#pragma unroll
        for (int ks = 0; ks < 2; ks++) {
            int kc = ks * 16 + qID * 2;
            uint32_t fah[2][4], fal[2][4], fbh[4][2], fbl[4][2];
#pragma unroll
            for (int am = 0; am < 2; am++) {
                int r0 = warpM * 32 + am * 16 + gID;
                fah[am][0] = *(const uint32_t*)&Ah[r0][kc];
                fah[am][1] = *(const uint32_t*)&Ah[r0 + 8][kc];
                fah[am][2] = *(const uint32_t*)&Ah[r0][kc + 8];
                fah[am][3] = *(const uint32_t*)&Ah[r0 + 8][kc + 8];
                fal[am][0] = *(const uint32_t*)&Al[r0][kc];
                fal[am][1] = *(const uint32_t*)&Al[r0 + 8][kc];
                fal[am][2] = *(const uint32_t*)&Al[r0][kc + 8];
                fal[am][3] = *(const uint32_t*)&Al[r0 + 8][kc + 8];
            }
#pragma unroll
            for (int bn = 0; bn < 4; bn++) {
                int n0 = warpN * 32 + bn * 8 + gID;
                fbh[bn][0] = *(const uint32_t*)&Bh[n0][kc];
                fbh[bn][1] = *(const uint32_t*)&Bh[n0][kc + 8];
                fbl[bn][0] = *(const uint32_t*)&Bl[n0][kc];
                fbl[bn][1] = *(const uint32_t*)&Bl[n0][kc + 8];
            }
#pragma unroll
            for (int am = 0; am < 2; am++)
#pragma unroll
                for (int bn = 0; bn < 4; bn++) {
                    mma16816(acc[am][bn], fah[am], fbh[bn]);
                    mma16816(acc[am][bn], fal[am], fbh[bn]);
                    mma16816(acc[am][bn], fah[am], fbl[bn]);
                }
        }
    }
#pragma unroll
    for (int am = 0; am < 2; am++) {
        int r0 = bm * 128 + warpM * 32 + am * 16 + gID;
        float d0 = rsqrtf(g_deg[z][r0]);
        float d1 = rsqrtf(g_deg[z][r0 + 8]);
        float s0 = d0 * d0, s1 = d1 * d1;
        int f0 = g_src[z][r0], f1 = g_src[z][r0 + 8];
#pragma unroll
        for (int bn = 0; bn < 4; bn++) {
            int cg = bnn * 64 + warpN * 32 + bn * 8 + qID * 2;
            float2 bb = *(const float2*)&b2[cg];
            size_t o0 = ((size_t)z * BB + r0) * OUTD + cg;
            size_t o1 = ((size_t)z * BB + r0 + 8) * OUTD + cg;
            float* p = acc[am][bn];
            if (f0) *(float2*)&g_xw2[o0] = make_float2(p[0], p[1]);
            *(float2*)&out[o0] = make_float2(s0 * p[0] + bb.x, s0 * p[1] + bb.y);
            if (f1) *(float2*)&g_xw2[o1] = make_float2(p[2], p[3]);
            *(float2*)&out[o1] = make_float2(s1 * p[2] + bb.x, s1 * p[3] + bb.y);
        }
    }
}

// ---------------- edge scatter into out + replay-state cleanup ----------------
__global__ void k_scatter2(float* __restrict__ out) {
    int r = blockIdx.y;
    int t = threadIdx.x;            // 256: one col each
    if (blockIdx.x == 128) {        // cleanup block: clear membership bits for next replay
        if (r == 0)
            for (int i = t; i < BB; i += 256) g_inb[g_bn[i]] = 0;
        return;
    }
    int c = g_cnt[r];
    for (int e = blockIdx.x; e < c; e += 128) {
        int s = g_ks[r][e], d = g_kd[r][e];
        float coeff = rsqrtf(g_deg[r][s]) * rsqrtf(g_deg[r][d]);
        const float* src = g_xw2 + ((size_t)(r * BB + s)) * OUTD;
        float* dst = out + (size_t)r * BB * OUTD + (size_t)d * OUTD;
        atomicAdd(dst + t, coeff * src[t]);
    }
}

// ---------------- launch ----------------
extern "C" void kernel_launch(void* const* d_in, const int* in_sizes, int n_in,
                              void* d_out, int out_size) {
    const float* feat  = (const float*)d_in[0];
    const float* W1    = (const float*)d_in[1];
    const float* b1    = (const float*)d_in[2];
    const float* W2    = (const float*)d_in[3];
    const float* b2    = (const float*)d_in[4];
    const float* gamma = (const float*)d_in[5];
    const float* beta  = (const float*)d_in[6];
    const void*  ei    = d_in[7];
    const void*  bn    = d_in[8];
    float* out = (float*)d_out;

    k_prep<<<64, 256>>>(bn);
    k_mask<<<dim3((EE / 4 + 255) / 256, RR), 256>>>(ei, bn);
    k_scanmap<<<RR, 1024>>>();
    k_gemm1<<<dim3(16, HID / 128, RR), 256>>>(feat, W1, b1);
    k_scatter1<<<dim3(128, RR), 256>>>();
    k_gemm2<<<dim3(16, OUTD / 64, RR), 256>>>(W2, b2, gamma, beta, out);
    k_scatter2<<<dim3(129, RR), 256>>>(out);
}

// round 14
// speedup vs baseline: 1.0347x; 1.0347x over previous
#include <cuda_runtime.h>
#include <cuda_bf16.h>
#include <stdint.h>

#define RR 3
#define NN 50000
#define EE 1000000
#define BB 2048
#define INP 256
#define HID 512
#define OUTD 256

#define SLD 40   // smem K-stride (elements): 20r+c hits all 32 banks distinctly

// ---------------- static scratch (no allocations allowed) ----------------
__device__ int g_bn[BB];
__device__ unsigned char g_inb[NN];
__device__ unsigned char g_app[RR][NN];
__device__ unsigned char g_src[RR][BB];     // row is an edge source (renumbered)
__device__ int g_newid[RR][NN];
__device__ int g_cnt[RR];
__device__ int g_ks[RR][EE];
__device__ int g_kd[RR][EE];
__device__ __align__(16) float g_deg[RR][BB];
__device__ __align__(16) float g_xw1[(size_t)RR * BB * HID];
__device__ __align__(16) float g_h[(size_t)RR * BB * HID];
__device__ __align__(16) float g_xw2[(size_t)RR * BB * OUTD];
__device__ __align__(16) float g_bnsum[RR][HID];
__device__ __align__(16) float g_bnsq[RR][HID];

// ---------------- helpers ----------------
__device__ __forceinline__ int detect64(const void* bn) {
    long long v = ((const long long*)bn)[0];   // sorted distinct ids: int32 view gives >= 2^32
    return (v >= 0 && v < NN) ? 1 : 0;
}

__device__ __forceinline__ void mma16816(float* c, const uint32_t* a, const uint32_t* b) {
    asm volatile(
        "mma.sync.aligned.m16n8k16.row.col.f32.bf16.bf16.f32 "
        "{%0,%1,%2,%3}, {%4,%5,%6,%7}, {%8,%9}, {%0,%1,%2,%3};"
        : "+f"(c[0]), "+f"(c[1]), "+f"(c[2]), "+f"(c[3])
        : "r"(a[0]), "r"(a[1]), "r"(a[2]), "r"(a[3]), "r"(b[0]), "r"(b[1]));
}

// split fp32x4 -> bf16 hi (truncate) + bf16 lo (rn of residual); 8B-aligned stores
__device__ __forceinline__ void split_store4(__nv_bfloat16* ph, __nv_bfloat16* pl, float4 v) {
    uint32_t b0 = __float_as_uint(v.x), b1 = __float_as_uint(v.y);
    uint32_t b2 = __float_as_uint(v.z), b3 = __float_as_uint(v.w);
    uint2 H;
    H.x = (b0 >> 16) | (b1 & 0xFFFF0000u);
    H.y = (b2 >> 16) | (b3 & 0xFFFF0000u);
    float l0 = v.x - __uint_as_float(b0 & 0xFFFF0000u);
    float l1 = v.y - __uint_as_float(b1 & 0xFFFF0000u);
    float l2 = v.z - __uint_as_float(b2 & 0xFFFF0000u);
    float l3 = v.w - __uint_as_float(b3 & 0xFFFF0000u);
    uint2 L;
    asm("cvt.rn.bf16x2.f32 %0, %1, %2;" : "=r"(L.x) : "f"(l1), "f"(l0));
    asm("cvt.rn.bf16x2.f32 %0, %1, %2;" : "=r"(L.y) : "f"(l3), "f"(l2));
    *(uint2*)ph = H;
    *(uint2*)pl = L;
}
__device__ __forceinline__ void split_store1(__nv_bfloat16* ph, __nv_bfloat16* pl, float v) {
    uint32_t b = __float_as_uint(v);
    *(uint16_t*)ph = (uint16_t)(b >> 16);
    float lo = v - __uint_as_float(b & 0xFFFF0000u);
    uint32_t lb;
    asm("cvt.rn.bf16x2.f32 %0, %1, %2;" : "=r"(lb) : "f"(0.f), "f"(lo));
    *(uint16_t*)pl = (uint16_t)lb;
}

// ---------------- prep: reset replay state + convert batch ids + membership ----------------
__global__ void k_prep(const void* __restrict__ bn) {
    int i = blockIdx.x * blockDim.x + threadIdx.x;   // 16384 threads
    for (int j = i; j < (RR * NN) / 4; j += 16384) ((int*)g_app)[j] = 0;
    if (i < (RR * BB) / 4) ((int*)g_src)[i] = 0;
    if (i < RR) g_cnt[i] = 0;
    if (i < RR * HID) { ((float*)g_bnsum)[i] = 0.f; ((float*)g_bnsq)[i] = 0.f; }
    if (i < BB) {
        int is64 = detect64(bn);
        int v = is64 ? (int)((const long long*)bn)[i] : ((const int*)bn)[i];
        g_bn[i] = v;
        g_inb[v] = 1;
    }
}

// ---------------- mask + compact kept edges (4 edges/thread) ----------------
__global__ void k_mask(const void* __restrict__ ei, const void* __restrict__ bn) {
    int r = blockIdx.y;
    int e0 = (blockIdx.x * blockDim.x + threadIdx.x) * 4;
    if (e0 >= EE) return;
    int is64 = detect64(bn);
    int s[4], d[4];
    if (is64) {
        const long long* b = (const long long*)ei + (size_t)r * 2 * EE;
        longlong2 s01 = *(const longlong2*)(b + e0);
        longlong2 s23 = *(const longlong2*)(b + e0 + 2);
        longlong2 d01 = *(const longlong2*)(b + EE + e0);
        longlong2 d23 = *(const longlong2*)(b + EE + e0 + 2);
        s[0] = (int)s01.x; s[1] = (int)s01.y; s[2] = (int)s23.x; s[3] = (int)s23.y;
        d[0] = (int)d01.x; d[1] = (int)d01.y; d[2] = (int)d23.x; d[3] = (int)d23.y;
    } else {
        const int* b = (const int*)ei + (size_t)r * 2 * EE;
        int4 sv = *(const int4*)(b + e0);
        int4 dv = *(const int4*)(b + EE + e0);
        s[0] = sv.x; s[1] = sv.y; s[2] = sv.z; s[3] = sv.w;
        d[0] = dv.x; d[1] = dv.y; d[2] = dv.z; d[3] = dv.w;
    }
#pragma unroll
    for (int q = 0; q < 4; q++) {
        if (g_inb[s[q]] & g_inb[d[q]]) {
            g_app[r][s[q]] = 1;
            g_app[r][d[q]] = 1;
            int j = atomicAdd(&g_cnt[r], 1);
            g_ks[r][j] = s[q];
            g_kd[r][j] = d[q];
        }
    }
}

// ---------------- scan (renumber) + map edges + smem degree histogram ----------------
__global__ void k_scanmap() {
    int r = blockIdx.x;
    int t = threadIdx.x;            // 1024 threads
    __shared__ int sh[1024];
    __shared__ float sdeg[BB];
    sdeg[t] = 1.0f;                 // self loop
    sdeg[t + 1024] = 1.0f;
    int v0 = g_bn[2 * t], v1 = g_bn[2 * t + 1];
    int a0 = g_app[r][v0], a1 = g_app[r][v1];
    int ps = a0 + a1;
    sh[t] = ps;
    __syncthreads();
    for (int off = 1; off < 1024; off <<= 1) {
        int val = (t >= off) ? sh[t - off] : 0;
        __syncthreads();
        sh[t] += val;
        __syncthreads();
    }
    int excl = sh[t] - ps;
    if (a0) g_newid[r][v0] = excl + a0 - 1;
    if (a1) g_newid[r][v1] = excl + a0 + a1 - 1;
    __syncthreads();
    int c = g_cnt[r];
    for (int j = t; j < c; j += 1024) {
        int s = g_newid[r][g_ks[r][j]];
        int d = g_newid[r][g_kd[r][j]];
        g_ks[r][j] = s;
        g_kd[r][j] = d;
        g_src[r][s] = 1;
        atomicAdd(&sdeg[d], 1.0f);
    }
    __syncthreads();
    g_deg[r][t] = sdeg[t];
    g_deg[r][t + 1024] = sdeg[t + 1024];
}

// ---------------- GEMM1 (mma.sync split-bf16): 64x64 tile, 128 thr, 4 warps 2x2 ----------
// xw1 = gather(feat)@W1 ; h = dinv^2*xw1 + b1 ; + partial BN stats of h0
__global__ void __launch_bounds__(128, 5) k_gemm1(
    const float* __restrict__ feat, const float* __restrict__ W1, const float* __restrict__ b1) {
    __shared__ __align__(16) __nv_bfloat16 Ah[64][SLD], Al[64][SLD];
    __shared__ __align__(16) __nv_bfloat16 Bh[64][SLD], Bl[64][SLD];
    __shared__ float sSum[64], sSq[64];
    const int z = blockIdx.z, bm = blockIdx.x, bnn = blockIdx.y;
    int tid = threadIdx.x, lane = tid & 31, wid = tid >> 5;
    int warpM = wid >> 1, warpN = wid & 1;
    int gID = lane >> 2, qID = lane & 3;
    if (tid < 64) { sSum[tid] = 0.f; sSq[tid] = 0.f; }

    float acc[2][4][4];
#pragma unroll
    for (int a = 0; a < 2; a++)
#pragma unroll
        for (int b = 0; b < 4; b++)
#pragma unroll
            for (int k = 0; k < 4; k++) acc[a][b][k] = 0.f;

    int ar = tid >> 1, ah = tid & 1;
    const float* arow = feat + ((size_t)z * NN + g_bn[bm * 64 + ar]) * INP + ah * 16;
    int nb = (tid & 15) * 4, kl = tid >> 4;   // B: 16 col-groups x 8 k-rows
    const float* wb = W1 + bnn * 64 + nb;

    for (int c = 0; c < INP / 32; c++) {
        int k0 = c * 32;
        if (c) __syncthreads();
#pragma unroll
        for (int i = 0; i < 4; i++) {
            float4 v = *(const float4*)(arow + k0 + i * 4);
            int cc = ah * 16 + i * 4;
            split_store4(&Ah[ar][cc], &Al[ar][cc], v);
        }
#pragma unroll
        for (int i = 0; i < 4; i++) {
            int k = kl + i * 8;
            float4 v = *(const float4*)(wb + (size_t)(k0 + k) * HID);
            split_store1(&Bh[nb + 0][k], &Bl[nb + 0][k], v.x);
            split_store1(&Bh[nb + 1][k], &Bl[nb + 1][k], v.y);
            split_store1(&Bh[nb + 2][k], &Bl[nb + 2][k], v.z);
            split_store1(&Bh[nb + 3][k], &Bl[nb + 3][k], v.w);
        }
        __syncthreads();
#pragma unroll
        for (int ks = 0; ks < 2; ks++) {
            int kc = ks * 16 + qID * 2;
            uint32_t fah[2][4], fal[2][4], fbh[4][2], fbl[4][2];
#pragma unroll
            for (int am = 0; am < 2; am++) {
                int r0 = warpM * 32 + am * 16 + gID;
                fah[am][0] = *(const uint32_t*)&Ah[r0][kc];
                fah[am][1] = *(const uint32_t*)&Ah[r0 + 8][kc];
                fah[am][2] = *(const uint32_t*)&Ah[r0][kc + 8];
                fah[am][3] = *(const uint32_t*)&Ah[r0 + 8][kc + 8];
                fal[am][0] = *(const uint32_t*)&Al[r0][kc];
                fal[am][1] = *(const uint32_t*)&Al[r0 + 8][kc];
                fal[am][2] = *(const uint32_t*)&Al[r0][kc + 8];
                fal[am][3] = *(const uint32_t*)&Al[r0 + 8][kc + 8];
            }
#pragma unroll
            for (int bn = 0; bn < 4; bn++) {
                int n0 = warpN * 32 + bn * 8 + gID;
                fbh[bn][0] = *(const uint32_t*)&Bh[n0][kc];
                fbh[bn][1] = *(const uint32_t*)&Bh[n0][kc + 8];
                fbl[bn][0] = *(const uint32_t*)&Bl[n0][kc];
                fbl[bn][1] = *(const uint32_t*)&Bl[n0][kc + 8];
            }
#pragma unroll
            for (int am = 0; am < 2; am++)
#pragma unroll
                for (int bn = 0; bn < 4; bn++) {
                    mma16816(acc[am][bn], fah[am], fbh[bn]);
                    mma16816(acc[am][bn], fal[am], fbh[bn]);
                    mma16816(acc[am][bn], fah[am], fbl[bn]);
                }
        }
    }
    // epilogue: write xw1 (source rows only), h, and per-column BN partials
    float csum[4][2] = {}, csq[4][2] = {};
#pragma unroll
    for (int am = 0; am < 2; am++) {
        int r0 = bm * 64 + warpM * 32 + am * 16 + gID;
        float d0 = rsqrtf(g_deg[z][r0]);
        float d1 = rsqrtf(g_deg[z][r0 + 8]);
        float s0 = d0 * d0, s1 = d1 * d1;
        int f0 = g_src[z][r0], f1 = g_src[z][r0 + 8];
#pragma unroll
        for (int bn = 0; bn < 4; bn++) {
            int cg = bnn * 64 + warpN * 32 + bn * 8 + qID * 2;
            float2 bb = *(const float2*)&b1[cg];
            size_t o0 = ((size_t)z * BB + r0) * HID + cg;
            size_t o1 = ((size_t)z * BB + r0 + 8) * HID + cg;
            float* p = acc[am][bn];
            float h00 = s0 * p[0] + bb.x, h01 = s0 * p[1] + bb.y;
            float h10 = s1 * p[2] + bb.x, h11 = s1 * p[3] + bb.y;
            if (f0) *(float2*)&g_xw1[o0] = make_float2(p[0], p[1]);
            *(float2*)&g_h[o0] = make_float2(h00, h01);
            if (f1) *(float2*)&g_xw1[o1] = make_float2(p[2], p[3]);
            *(float2*)&g_h[o1] = make_float2(h10, h11);
            csum[bn][0] += h00 + h10; csum[bn][1] += h01 + h11;
            csq[bn][0] += h00 * h00 + h10 * h10; csq[bn][1] += h01 * h01 + h11 * h11;
        }
    }
#pragma unroll
    for (int bn = 0; bn < 4; bn++) {
        int cl = warpN * 32 + bn * 8 + qID * 2;
        atomicAdd(&sSum[cl], csum[bn][0]);     atomicAdd(&sSum[cl + 1], csum[bn][1]);
        atomicAdd(&sSq[cl], csq[bn][0]);       atomicAdd(&sSq[cl + 1], csq[bn][1]);
    }
    __syncthreads();
    if (tid < 64) {
        atomicAdd(&g_bnsum[z][bnn * 64 + tid], sSum[tid]);
        atomicAdd(&g_bnsq[z][bnn * 64 + tid], sSq[tid]);
    }
}

// ---------------- edge scatter into h + telescoping BN stat corrections ----------------
// sum of ((old+a)^2 - old^2) over the atomic serialization telescopes to hfin^2 - h0^2: exact.
__global__ void k_scatter1() {
    int r = blockIdx.y;
    int c = g_cnt[r];
    int t = threadIdx.x;            // 256: cols t and t+256
    float s0 = 0.f, q0 = 0.f, s1 = 0.f, q1 = 0.f;
    for (int e = blockIdx.x; e < c; e += 128) {
        int s = g_ks[r][e], d = g_kd[r][e];
        float coeff = rsqrtf(g_deg[r][s]) * rsqrtf(g_deg[r][d]);
        const float* src = g_xw1 + ((size_t)(r * BB + s)) * HID;
        float* dst = g_h + ((size_t)(r * BB + d)) * HID;
        float a0 = coeff * src[t];
        float o0 = atomicAdd(dst + t, a0);
        s0 += a0; q0 += a0 * (2.f * o0 + a0);
        float a1 = coeff * src[t + 256];
        float o1 = atomicAdd(dst + t + 256, a1);
        s1 += a1; q1 += a1 * (2.f * o1 + a1);
    }
    if (blockIdx.x < (unsigned)c) {
        atomicAdd(&g_bnsum[r][t], s0);       atomicAdd(&g_bnsq[r][t], q0);
        atomicAdd(&g_bnsum[r][t + 256], s1); atomicAdd(&g_bnsq[r][t + 256], q1);
    }
}

// ---------------- GEMM2 (mma.sync split-bf16): 64x64 tile, 128 thr, 4 warps 2x2 ----------
// xw2 = BN(h)@W2 ; out = dinv^2*xw2 + b2 ; BN affine computed in-prologue from stats
__global__ void __launch_bounds__(128, 5) k_gemm2(
    const float* __restrict__ W2, const float* __restrict__ b2,
    const float* __restrict__ gamma, const float* __restrict__ beta,
    float* __restrict__ out) {
    __shared__ __align__(16) __nv_bfloat16 Ah[64][SLD], Al[64][SLD];
    __shared__ __align__(16) __nv_bfloat16 Bh[64][SLD], Bl[64][SLD];
    __shared__ __align__(16) float sBa[HID], sBb[HID];
    const int z = blockIdx.z, bm = blockIdx.x, bnn = blockIdx.y;
    int tid = threadIdx.x, lane = tid & 31, wid = tid >> 5;
    int warpM = wid >> 1, warpN = wid & 1;
    int gID = lane >> 2, qID = lane & 3;

    // BN affine from stats (redundant per block; tiny)
    for (int i = tid; i < HID; i += 128) {
        float m = g_bnsum[z][i] * (1.0f / BB);
        float v = g_bnsq[z][i] * (1.0f / BB) - m * m;
        float istd = rsqrtf(v + 1e-5f);
        float a = gamma[i] * istd;
        sBa[i] = a;
        sBb[i] = beta[i] - m * a;
    }
    __syncthreads();

    float acc[2][4][4];
#pragma unroll
    for (int a = 0; a < 2; a++)
#pragma unroll
        for (int b = 0; b < 4; b++)
#pragma unroll
            for (int k = 0; k < 4; k++) acc[a][b][k] = 0.f;

    int ar = tid >> 1, ah = tid & 1;
    const float* arow = g_h + ((size_t)(z * BB + bm * 64 + ar)) * HID + ah * 16;
    int nb = (tid & 15) * 4, kl = tid >> 4;
    const float* wb = W2 + bnn * 64 + nb;

    for (int c = 0; c < HID / 32; c++) {
        int k0 = c * 32;
        if (c) __syncthreads();
#pragma unroll
        for (int i = 0; i < 4; i++) {
            int cc = ah * 16 + i * 4;
            float4 hv = *(const float4*)(arow + k0 + i * 4);
            float4 av = *(const float4*)&sBa[k0 + cc];
            float4 bv = *(const float4*)&sBb[k0 + cc];
            float4 v;
            v.x = hv.x * av.x + bv.x; v.y = hv.y * av.y + bv.y;
            v.z = hv.z * av.z + bv.z; v.w = hv.w * av.w + bv.w;
            split_store4(&Ah[ar][cc], &Al[ar][cc], v);
        }
#pragma unroll
        for (int i = 0; i < 4; i++) {
            int k = kl + i * 8;
            float4 v = *(const float4*)(wb + (size_t)(k0 + k) * OUTD);
            split_store1(&Bh[nb + 0][k], &Bl[nb + 0][k], v.x);
            split_store1(&Bh[nb + 1][k], &Bl[nb + 1][k], v.y);
            split_store1(&Bh[nb + 2][k], &Bl[nb + 2][k], v.z);
            split_store1(&Bh[nb + 3][k], &Bl[nb + 3][k], v.w);
        }
        __syncthreads();
#pragma unroll
        for (int ks = 0; ks < 2; ks++) {
            int kc = ks * 16 + qID * 2;
            uint32_t fah[2][4], fal[2][4], fbh[4][2], fbl[4][2];
#pragma unroll
            for (int am = 0; am < 2; am++) {
                int r0 = warpM * 32 + am * 16 + gID;
                fah[am][0] = *(const uint32_t*)&Ah[r0][kc];
                fah[am][1] = *(const uint32_t*)&Ah[r0 + 8][kc];
                fah[am][2] = *(const uint32_t*)&Ah[r0][kc + 8];
                fah[am][3] = *(const uint32_t*)&Ah[r0 + 8][kc + 8];
                fal[am][0] = *(const uint32_t*)&Al[r0][kc];
                fal[am][1] = *(const uint32_t*)&Al[r0 + 8][kc];
                fal[am][2] = *(const uint32_t*)&Al[r0][kc + 8];
                fal[am][3] = *(const uint32_t*)&Al[r0 + 8][kc + 8];
            }
#pragma unroll
            for (int bn = 0; bn < 4; bn++) {
                int n0 = warpN * 32 + bn * 8 + gID;
                fbh[bn][0] = *(const uint32_t*)&Bh[n0][kc];
                fbh[bn][1] = *(const uint32_t*)&Bh[n0][kc + 8];
                fbl[bn][0] = *(const uint32_t*)&Bl[n0][kc];
                fbl[bn][1] = *(const uint32_t*)&Bl[n0][kc + 8];
            }
#pragma unroll
            for (int am = 0; am < 2; am++)
#pragma unroll
                for (int bn = 0; bn < 4; bn++) {
                    mma16816(acc[am][bn], fah[am], fbh[bn]);
                    mma16816(acc[am][bn], fal[am], fbh[bn]);
                    mma16816(acc[am][bn], fah[am], fbl[bn]);
                }
        }
    }
#pragma unroll
    for (int am = 0; am < 2; am++) {
        int r0 = bm * 64 + warpM * 32 + am * 16 + gID;
        float d0 = rsqrtf(g_deg[z][r0]);
        float d1 = rsqrtf(g_deg[z][r0 + 8]);
        float s0 = d0 * d0, s1 = d1 * d1;
        int f0 = g_src[z][r0], f1 = g_src[z][r0 + 8];
#pragma unroll
        for (int bn = 0; bn < 4; bn++) {
            int cg = bnn * 64 + warpN * 32 + bn * 8 + qID * 2;
            float2 bb = *(const float2*)&b2[cg];
            size_t o0 = ((size_t)z * BB + r0) * OUTD + cg;
            size_t o1 = ((size_t)z * BB + r0 + 8) * OUTD + cg;
            float* p = acc[am][bn];
            if (f0) *(float2*)&g_xw2[o0] = make_float2(p[0], p[1]);
            *(float2*)&out[o0] = make_float2(s0 * p[0] + bb.x, s0 * p[1] + bb.y);
            if (f1) *(float2*)&g_xw2[o1] = make_float2(p[2], p[3]);
            *(float2*)&out[o1] = make_float2(s1 * p[2] + bb.x, s1 * p[3] + bb.y);
        }
    }
}

// ---------------- edge scatter into out + replay-state cleanup ----------------
__global__ void k_scatter2(float* __restrict__ out) {
    int r = blockIdx.y;
    int t = threadIdx.x;            // 256: one col each
    if (blockIdx.x == 128) {        // cleanup block: clear membership bits for next replay
        if (r == 0)
            for (int i = t; i < BB; i += 256) g_inb[g_bn[i]] = 0;
        return;
    }
    int c = g_cnt[r];
    for (int e = blockIdx.x; e < c; e += 128) {
        int s = g_ks[r][e], d = g_kd[r][e];
        float coeff = rsqrtf(g_deg[r][s]) * rsqrtf(g_deg[r][d]);
        const float* src = g_xw2 + ((size_t)(r * BB + s)) * OUTD;
        float* dst = out + (size_t)r * BB * OUTD + (size_t)d * OUTD;
        atomicAdd(dst + t, coeff * src[t]);
    }
}

// ---------------- launch ----------------
extern "C" void kernel_launch(void* const* d_in, const int* in_sizes, int n_in,
                              void* d_out, int out_size) {
    const float* feat  = (const float*)d_in[0];
    const float* W1    = (const float*)d_in[1];
    const float* b1    = (const float*)d_in[2];
    const float* W2    = (const float*)d_in[3];
    const float* b2    = (const float*)d_in[4];
    const float* gamma = (const float*)d_in[5];
    const float* beta  = (const float*)d_in[6];
    const void*  ei    = d_in[7];
    const void*  bn    = d_in[8];
    float* out = (float*)d_out;

    k_prep<<<64, 256>>>(bn);
    k_mask<<<dim3((EE / 4 + 255) / 256, RR), 256>>>(ei, bn);
    k_scanmap<<<RR, 1024>>>();
    k_gemm1<<<dim3(BB / 64, HID / 64, RR), 128>>>(feat, W1, b1);
    k_scatter1<<<dim3(128, RR), 256>>>();
    k_gemm2<<<dim3(BB / 64, OUTD / 64, RR), 128>>>(W2, b2, gamma, beta, out);
    k_scatter2<<<dim3(129, RR), 256>>>(out);
}

// round 15
// speedup vs baseline: 1.4273x; 1.3795x over previous
#include <cuda_runtime.h>
#include <cuda_bf16.h>
#include <stdint.h>

#define RR 3
#define NN 50000
#define EE 1000000
#define BB 2048
#define INP 256
#define HID 512
#define OUTD 256

#define SLD 40    // A smem k-stride (elems): 20r+c covers all 32 banks
#define SLDB 72   // B smem n-stride (elems): 36 words/row -> banks 4r, conflict-free

// ---------------- static scratch (no allocations allowed) ----------------
__device__ int g_bn[BB];
__device__ unsigned char g_inb[NN];
__device__ unsigned char g_app[RR][NN];
__device__ unsigned char g_src[RR][BB];     // row is an edge source (renumbered)
__device__ int g_newid[RR][NN];
__device__ int g_cnt[RR];
__device__ int g_ks[RR][EE];
__device__ int g_kd[RR][EE];
__device__ __align__(16) float g_deg[RR][BB];
__device__ __align__(16) float g_xw1[(size_t)RR * BB * HID];
__device__ __align__(16) float g_h[(size_t)RR * BB * HID];
__device__ __align__(16) float g_xw2[(size_t)RR * BB * OUTD];
__device__ __align__(16) float g_bnsum[RR][HID];
__device__ __align__(16) float g_bnsq[RR][HID];

// ---------------- helpers ----------------
__device__ __forceinline__ int detect64(const void* bn) {
    long long v = ((const long long*)bn)[0];   // sorted distinct ids: int32 view gives >= 2^32
    return (v >= 0 && v < NN) ? 1 : 0;
}

__device__ __forceinline__ void mma16816(float* c, const uint32_t* a, const uint32_t* b) {
    asm volatile(
        "mma.sync.aligned.m16n8k16.row.col.f32.bf16.bf16.f32 "
        "{%0,%1,%2,%3}, {%4,%5,%6,%7}, {%8,%9}, {%0,%1,%2,%3};"
        : "+f"(c[0]), "+f"(c[1]), "+f"(c[2]), "+f"(c[3])
        : "r"(a[0]), "r"(a[1]), "r"(a[2]), "r"(a[3]), "r"(b[0]), "r"(b[1]));
}
__device__ __forceinline__ void ldsm_x4(uint32_t* d, uint32_t addr) {
    asm volatile("ldmatrix.sync.aligned.m8n8.x4.shared.b16 {%0,%1,%2,%3}, [%4];"
        : "=r"(d[0]), "=r"(d[1]), "=r"(d[2]), "=r"(d[3]) : "r"(addr));
}
__device__ __forceinline__ void ldsm_x4t(uint32_t* d, uint32_t addr) {
    asm volatile("ldmatrix.sync.aligned.m8n8.x4.trans.shared.b16 {%0,%1,%2,%3}, [%4];"
        : "=r"(d[0]), "=r"(d[1]), "=r"(d[2]), "=r"(d[3]) : "r"(addr));
}

// split fp32x4 -> bf16 hi (truncate) + bf16 lo (rn of residual); 8B-aligned stores
__device__ __forceinline__ void split_store4(__nv_bfloat16* ph, __nv_bfloat16* pl, float4 v) {
    uint32_t b0 = __float_as_uint(v.x), b1 = __float_as_uint(v.y);
    uint32_t b2 = __float_as_uint(v.z), b3 = __float_as_uint(v.w);
    uint2 H;
    H.x = (b0 >> 16) | (b1 & 0xFFFF0000u);
    H.y = (b2 >> 16) | (b3 & 0xFFFF0000u);
    float l0 = v.x - __uint_as_float(b0 & 0xFFFF0000u);
    float l1 = v.y - __uint_as_float(b1 & 0xFFFF0000u);
    float l2 = v.z - __uint_as_float(b2 & 0xFFFF0000u);
    float l3 = v.w - __uint_as_float(b3 & 0xFFFF0000u);
    uint2 L;
    asm("cvt.rn.bf16x2.f32 %0, %1, %2;" : "=r"(L.x) : "f"(l1), "f"(l0));
    asm("cvt.rn.bf16x2.f32 %0, %1, %2;" : "=r"(L.y) : "f"(l3), "f"(l2));
    *(uint2*)ph = H;
    *(uint2*)pl = L;
}

// ---------------- prep: reset replay state + convert batch ids + membership ----------------
__global__ void k_prep(const void* __restrict__ bn) {
    int i = blockIdx.x * blockDim.x + threadIdx.x;   // 16384 threads
    for (int j = i; j < (RR * NN) / 4; j += 16384) ((int*)g_app)[j] = 0;
    if (i < (RR * BB) / 4) ((int*)g_src)[i] = 0;
    if (i < RR) g_cnt[i] = 0;
    if (i < RR * HID) { ((float*)g_bnsum)[i] = 0.f; ((float*)g_bnsq)[i] = 0.f; }
    if (i < BB) {
        int is64 = detect64(bn);
        int v = is64 ? (int)((const long long*)bn)[i] : ((const int*)bn)[i];
        g_bn[i] = v;
        g_inb[v] = 1;
    }
}

// ---------------- mask + compact kept edges (4 edges/thread) ----------------
__global__ void k_mask(const void* __restrict__ ei, const void* __restrict__ bn) {
    int r = blockIdx.y;
    int e0 = (blockIdx.x * blockDim.x + threadIdx.x) * 4;
    if (e0 >= EE) return;
    int is64 = detect64(bn);
    int s[4], d[4];
    if (is64) {
        const long long* b = (const long long*)ei + (size_t)r * 2 * EE;
        longlong2 s01 = *(const longlong2*)(b + e0);
        longlong2 s23 = *(const longlong2*)(b + e0 + 2);
        longlong2 d01 = *(const longlong2*)(b + EE + e0);
        longlong2 d23 = *(const longlong2*)(b + EE + e0 + 2);
        s[0] = (int)s01.x; s[1] = (int)s01.y; s[2] = (int)s23.x; s[3] = (int)s23.y;
        d[0] = (int)d01.x; d[1] = (int)d01.y; d[2] = (int)d23.x; d[3] = (int)d23.y;
    } else {
        const int* b = (const int*)ei + (size_t)r * 2 * EE;
        int4 sv = *(const int4*)(b + e0);
        int4 dv = *(const int4*)(b + EE + e0);
        s[0] = sv.x; s[1] = sv.y; s[2] = sv.z; s[3] = sv.w;
        d[0] = dv.x; d[1] = dv.y; d[2] = dv.z; d[3] = dv.w;
    }
#pragma unroll
    for (int q = 0; q < 4; q++) {
        if (g_inb[s[q]] & g_inb[d[q]]) {
            g_app[r][s[q]] = 1;
            g_app[r][d[q]] = 1;
            int j = atomicAdd(&g_cnt[r], 1);
            g_ks[r][j] = s[q];
            g_kd[r][j] = d[q];
        }
    }
}

// ---------------- scan (renumber) + map edges + smem degree histogram ----------------
__global__ void k_scanmap() {
    int r = blockIdx.x;
    int t = threadIdx.x;            // 1024 threads
    __shared__ int sh[1024];
    __shared__ float sdeg[BB];
    sdeg[t] = 1.0f;                 // self loop
    sdeg[t + 1024] = 1.0f;
    int v0 = g_bn[2 * t], v1 = g_bn[2 * t + 1];
    int a0 = g_app[r][v0], a1 = g_app[r][v1];
    int ps = a0 + a1;
    sh[t] = ps;
    __syncthreads();
    for (int off = 1; off < 1024; off <<= 1) {
        int val = (t >= off) ? sh[t - off] : 0;
        __syncthreads();
        sh[t] += val;
        __syncthreads();
    }
    int excl = sh[t] - ps;
    if (a0) g_newid[r][v0] = excl + a0 - 1;
    if (a1) g_newid[r][v1] = excl + a0 + a1 - 1;
    __syncthreads();
    int c = g_cnt[r];
    for (int j = t; j < c; j += 1024) {
        int s = g_newid[r][g_ks[r][j]];
        int d = g_newid[r][g_kd[r][j]];
        g_ks[r][j] = s;
        g_kd[r][j] = d;
        g_src[r][s] = 1;
        atomicAdd(&sdeg[d], 1.0f);
    }
    __syncthreads();
    g_deg[r][t] = sdeg[t];
    g_deg[r][t + 1024] = sdeg[t + 1024];
}

// ---------------- GEMM1: 64x64 tile, 128 thr, 4 warps 2x2, ldmatrix + prefetch ----------
// xw1 = gather(feat)@W1 ; h = dinv^2*xw1 + b1 ; + partial BN stats of h0
__global__ void __launch_bounds__(128, 4) k_gemm1(
    const float* __restrict__ feat, const float* __restrict__ W1, const float* __restrict__ b1) {
    __shared__ __align__(16) __nv_bfloat16 Ah[64][SLD], Al[64][SLD];   // [m][k]
    __shared__ __align__(16) __nv_bfloat16 Bh[32][SLDB], Bl[32][SLDB]; // [k][n]
    __shared__ float sSum[64], sSq[64];
    const int z = blockIdx.z, bm = blockIdx.x, bnn = blockIdx.y;
    int tid = threadIdx.x, lane = tid & 31, wid = tid >> 5;
    int warpM = wid >> 1, warpN = wid & 1;
    int gID = lane >> 2, qID = lane & 3;
    if (tid < 64) { sSum[tid] = 0.f; sSq[tid] = 0.f; }

    uint32_t sAh = (uint32_t)__cvta_generic_to_shared(&Ah[0][0]);
    uint32_t sAl = (uint32_t)__cvta_generic_to_shared(&Al[0][0]);
    uint32_t sBh = (uint32_t)__cvta_generic_to_shared(&Bh[0][0]);
    uint32_t sBl = (uint32_t)__cvta_generic_to_shared(&Bl[0][0]);
    int lr = lane & 7, lq = lane >> 3;
    uint32_t aOff = ((lr + 8 * (lq & 1)) * SLD + 8 * (lq >> 1)) * 2;
    uint32_t bOff = ((lr + 8 * (lq & 1)) * SLDB + 8 * (lq >> 1)) * 2;

    float acc[2][4][4];
#pragma unroll
    for (int a = 0; a < 2; a++)
#pragma unroll
        for (int b = 0; b < 4; b++)
#pragma unroll
            for (int k = 0; k < 4; k++) acc[a][b][k] = 0.f;

    int ar = tid >> 1, ahalf = tid & 1;
    const float* arow = feat + ((size_t)z * NN + g_bn[bm * 64 + ar]) * INP + ahalf * 16;
    int nb = (tid & 15) * 4, kl = tid >> 4;   // B: n group nb, k rows kl+8i
    const float* wb = W1 + bnn * 64 + nb;

    float4 pa[4], pb[4];
#pragma unroll
    for (int i = 0; i < 4; i++) {
        pa[i] = *(const float4*)(arow + i * 4);
        pb[i] = *(const float4*)(wb + (size_t)(kl + 8 * i) * HID);
    }

    const int C = INP / 32;   // 8
    for (int c = 0; c < C; c++) {
#pragma unroll
        for (int i = 0; i < 4; i++) {
            int cc = ahalf * 16 + i * 4;
            split_store4(&Ah[ar][cc], &Al[ar][cc], pa[i]);
            int kk = kl + 8 * i;
            split_store4(&Bh[kk][nb], &Bl[kk][nb], pb[i]);
        }
        __syncthreads();
        if (c + 1 < C) {
            int k0g = (c + 1) * 32;
#pragma unroll
            for (int i = 0; i < 4; i++) {
                pa[i] = *(const float4*)(arow + k0g + i * 4);
                pb[i] = *(const float4*)(wb + (size_t)(k0g + kl + 8 * i) * HID);
            }
        }
#pragma unroll
        for (int ks = 0; ks < 2; ks++) {
            uint32_t fah[2][4], fal[2][4], fbh[4][2], fbl[4][2];
#pragma unroll
            for (int am = 0; am < 2; am++) {
                uint32_t ra = (((warpM * 32 + am * 16) * SLD + ks * 16) << 1) + aOff;
                ldsm_x4(fah[am], sAh + ra);
                ldsm_x4(fal[am], sAl + ra);
            }
#pragma unroll
            for (int bnp = 0; bnp < 2; bnp++) {
                uint32_t rb = (((ks * 16) * SLDB + warpN * 32 + bnp * 16) << 1) + bOff;
                uint32_t t4[4];
                ldsm_x4t(t4, sBh + rb);
                fbh[2 * bnp][0] = t4[0]; fbh[2 * bnp][1] = t4[1];
                fbh[2 * bnp + 1][0] = t4[2]; fbh[2 * bnp + 1][1] = t4[3];
                ldsm_x4t(t4, sBl + rb);
                fbl[2 * bnp][0] = t4[0]; fbl[2 * bnp][1] = t4[1];
                fbl[2 * bnp + 1][0] = t4[2]; fbl[2 * bnp + 1][1] = t4[3];
            }
#pragma unroll
            for (int am = 0; am < 2; am++)
#pragma unroll
                for (int bn = 0; bn < 4; bn++) {
                    mma16816(acc[am][bn], fah[am], fbh[bn]);
                    mma16816(acc[am][bn], fal[am], fbh[bn]);
                    mma16816(acc[am][bn], fah[am], fbl[bn]);
                }
        }
        if (c + 1 < C) __syncthreads();
    }
    // epilogue: write xw1 (source rows only), h, and per-column BN partials
    float csum[4][2] = {}, csq[4][2] = {};
#pragma unroll
    for (int am = 0; am < 2; am++) {
        int r0 = bm * 64 + warpM * 32 + am * 16 + gID;
        float d0 = rsqrtf(g_deg[z][r0]);
        float d1 = rsqrtf(g_deg[z][r0 + 8]);
        float s0 = d0 * d0, s1 = d1 * d1;
        int f0 = g_src[z][r0], f1 = g_src[z][r0 + 8];
#pragma unroll
        for (int bn = 0; bn < 4; bn++) {
            int cg = bnn * 64 + warpN * 32 + bn * 8 + qID * 2;
            float2 bb = *(const float2*)&b1[cg];
            size_t o0 = ((size_t)z * BB + r0) * HID + cg;
            size_t o1 = ((size_t)z * BB + r0 + 8) * HID + cg;
            float* p = acc[am][bn];
            float h00 = s0 * p[0] + bb.x, h01 = s0 * p[1] + bb.y;
            float h10 = s1 * p[2] + bb.x, h11 = s1 * p[3] + bb.y;
            if (f0) *(float2*)&g_xw1[o0] = make_float2(p[0], p[1]);
            *(float2*)&g_h[o0] = make_float2(h00, h01);
            if (f1) *(float2*)&g_xw1[o1] = make_float2(p[2], p[3]);
            *(float2*)&g_h[o1] = make_float2(h10, h11);
            csum[bn][0] += h00 + h10; csum[bn][1] += h01 + h11;
            csq[bn][0] += h00 * h00 + h10 * h10; csq[bn][1] += h01 * h01 + h11 * h11;
        }
    }
#pragma unroll
    for (int bn = 0; bn < 4; bn++) {
        int cl = warpN * 32 + bn * 8 + qID * 2;
        atomicAdd(&sSum[cl], csum[bn][0]);     atomicAdd(&sSum[cl + 1], csum[bn][1]);
        atomicAdd(&sSq[cl], csq[bn][0]);       atomicAdd(&sSq[cl + 1], csq[bn][1]);
    }
    __syncthreads();
    if (tid < 64) {
        atomicAdd(&g_bnsum[z][bnn * 64 + tid], sSum[tid]);
        atomicAdd(&g_bnsq[z][bnn * 64 + tid], sSq[tid]);
    }
}

// ---------------- edge scatter into h + telescoping BN stat corrections ----------------
// sum of ((old+a)^2 - old^2) over the atomic serialization telescopes to hfin^2 - h0^2: exact.
__global__ void k_scatter1() {
    int r = blockIdx.y;
    int c = g_cnt[r];
    int t = threadIdx.x;            // 256: cols t and t+256
    float s0 = 0.f, q0 = 0.f, s1 = 0.f, q1 = 0.f;
    for (int e = blockIdx.x; e < c; e += 128) {
        int s = g_ks[r][e], d = g_kd[r][e];
        float coeff = rsqrtf(g_deg[r][s]) * rsqrtf(g_deg[r][d]);
        const float* src = g_xw1 + ((size_t)(r * BB + s)) * HID;
        float* dst = g_h + ((size_t)(r * BB + d)) * HID;
        float a0 = coeff * src[t];
        float o0 = atomicAdd(dst + t, a0);
        s0 += a0; q0 += a0 * (2.f * o0 + a0);
        float a1 = coeff * src[t + 256];
        float o1 = atomicAdd(dst + t + 256, a1);
        s1 += a1; q1 += a1 * (2.f * o1 + a1);
    }
    if (blockIdx.x < (unsigned)c) {
        atomicAdd(&g_bnsum[r][t], s0);       atomicAdd(&g_bnsq[r][t], q0);
        atomicAdd(&g_bnsum[r][t + 256], s1); atomicAdd(&g_bnsq[r][t + 256], q1);
    }
}

// ---------------- GEMM2: 64x64 tile, 128 thr, ldmatrix + prefetch; BN affine in prologue ----
// xw2 = BN(h)@W2 ; out = dinv^2*xw2 + b2
__global__ void __launch_bounds__(128, 4) k_gemm2(
    const float* __restrict__ W2, const float* __restrict__ b2,
    const float* __restrict__ gamma, const float* __restrict__ beta,
    float* __restrict__ out) {
    __shared__ __align__(16) __nv_bfloat16 Ah[64][SLD], Al[64][SLD];
    __shared__ __align__(16) __nv_bfloat16 Bh[32][SLDB], Bl[32][SLDB];
    __shared__ __align__(16) float sBa[HID], sBb[HID];
    const int z = blockIdx.z, bm = blockIdx.x, bnn = blockIdx.y;
    int tid = threadIdx.x, lane = tid & 31, wid = tid >> 5;
    int warpM = wid >> 1, warpN = wid & 1;
    int gID = lane >> 2, qID = lane & 3;

    // BN affine from stats (redundant per block; tiny)
    for (int i = tid; i < HID; i += 128) {
        float m = g_bnsum[z][i] * (1.0f / BB);
        float v = g_bnsq[z][i] * (1.0f / BB) - m * m;
        float istd = rsqrtf(v + 1e-5f);
        float a = gamma[i] * istd;
        sBa[i] = a;
        sBb[i] = beta[i] - m * a;
    }

    uint32_t sAh = (uint32_t)__cvta_generic_to_shared(&Ah[0][0]);
    uint32_t sAl = (uint32_t)__cvta_generic_to_shared(&Al[0][0]);
    uint32_t sBh = (uint32_t)__cvta_generic_to_shared(&Bh[0][0]);
    uint32_t sBl = (uint32_t)__cvta_generic_to_shared(&Bl[0][0]);
    int lr = lane & 7, lq = lane >> 3;
    uint32_t aOff = ((lr + 8 * (lq & 1)) * SLD + 8 * (lq >> 1)) * 2;
    uint32_t bOff = ((lr + 8 * (lq & 1)) * SLDB + 8 * (lq >> 1)) * 2;

    float acc[2][4][4];
#pragma unroll
    for (int a = 0; a < 2; a++)
#pragma unroll
        for (int b = 0; b < 4; b++)
#pragma unroll
            for (int k = 0; k < 4; k++) acc[a][b][k] = 0.f;

    int ar = tid >> 1, ahalf = tid & 1;
    const float* arow = g_h + ((size_t)(z * BB + bm * 64 + ar)) * HID + ahalf * 16;
    int nb = (tid & 15) * 4, kl = tid >> 4;
    const float* wb = W2 + bnn * 64 + nb;

    float4 pa[4], pb[4];
#pragma unroll
    for (int i = 0; i < 4; i++) {
        pa[i] = *(const float4*)(arow + i * 4);
        pb[i] = *(const float4*)(wb + (size_t)(kl + 8 * i) * OUTD);
    }
    __syncthreads();   // sBa/sBb ready before first store's affine reads

    const int C = HID / 32;   // 16
    for (int c = 0; c < C; c++) {
        int k0g = c * 32;
#pragma unroll
        for (int i = 0; i < 4; i++) {
            int cc = ahalf * 16 + i * 4;
            float4 av = *(const float4*)&sBa[k0g + cc];
            float4 bv = *(const float4*)&sBb[k0g + cc];
            float4 v;
            v.x = pa[i].x * av.x + bv.x; v.y = pa[i].y * av.y + bv.y;
            v.z = pa[i].z * av.z + bv.z; v.w = pa[i].w * av.w + bv.w;
            split_store4(&Ah[ar][cc], &Al[ar][cc], v);
            int kk = kl + 8 * i;
            split_store4(&Bh[kk][nb], &Bl[kk][nb], pb[i]);
        }
        __syncthreads();
        if (c + 1 < C) {
            int k1 = (c + 1) * 32;
#pragma unroll
            for (int i = 0; i < 4; i++) {
                pa[i] = *(const float4*)(arow + k1 + i * 4);
                pb[i] = *(const float4*)(wb + (size_t)(k1 + kl + 8 * i) * OUTD);
            }
        }
#pragma unroll
        for (int ks = 0; ks < 2; ks++) {
            uint32_t fah[2][4], fal[2][4], fbh[4][2], fbl[4][2];
#pragma unroll
            for (int am = 0; am < 2; am++) {
                uint32_t ra = (((warpM * 32 + am * 16) * SLD + ks * 16) << 1) + aOff;
                ldsm_x4(fah[am], sAh + ra);
                ldsm_x4(fal[am], sAl + ra);
            }
#pragma unroll
            for (int bnp = 0; bnp < 2; bnp++) {
                uint32_t rb = (((ks * 16) * SLDB + warpN * 32 + bnp * 16) << 1) + bOff;
                uint32_t t4[4];
                ldsm_x4t(t4, sBh + rb);
                fbh[2 * bnp][0] = t4[0]; fbh[2 * bnp][1] = t4[1];
                fbh[2 * bnp + 1][0] = t4[2]; fbh[2 * bnp + 1][1] = t4[3];
                ldsm_x4t(t4, sBl + rb);
                fbl[2 * bnp][0] = t4[0]; fbl[2 * bnp][1] = t4[1];
                fbl[2 * bnp + 1][0] = t4[2]; fbl[2 * bnp + 1][1] = t4[3];
            }
#pragma unroll
            for (int am = 0; am < 2; am++)
#pragma unroll
                for (int bn = 0; bn < 4; bn++) {
                    mma16816(acc[am][bn], fah[am], fbh[bn]);
                    mma16816(acc[am][bn], fal[am], fbh[bn]);
                    mma16816(acc[am][bn], fah[am], fbl[bn]);
                }
        }
        if (c + 1 < C) __syncthreads();
    }
#pragma unroll
    for (int am = 0; am < 2; am++) {
        int r0 = bm * 64 + warpM * 32 + am * 16 + gID;
        float d0 = rsqrtf(g_deg[z][r0]);
        float d1 = rsqrtf(g_deg[z][r0 + 8]);
        float s0 = d0 * d0, s1 = d1 * d1;
        int f0 = g_src[z][r0], f1 = g_src[z][r0 + 8];
#pragma unroll
        for (int bn = 0; bn < 4; bn++) {
            int cg = bnn * 64 + warpN * 32 + bn * 8 + qID * 2;
            float2 bb = *(const float2*)&b2[cg];
            size_t o0 = ((size_t)z * BB + r0) * OUTD + cg;
            size_t o1 = ((size_t)z * BB + r0 + 8) * OUTD + cg;
            float* p = acc[am][bn];
            if (f0) *(float2*)&g_xw2[o0] = make_float2(p[0], p[1]);
            *(float2*)&out[o0] = make_float2(s0 * p[0] + bb.x, s0 * p[1] + bb.y);
            if (f1) *(float2*)&g_xw2[o1] = make_float2(p[2], p[3]);
            *(float2*)&out[o1] = make_float2(s1 * p[2] + bb.x, s1 * p[3] + bb.y);
        }
    }
}

// ---------------- edge scatter into out + replay-state cleanup ----------------
__global__ void k_scatter2(float* __restrict__ out) {
    int r = blockIdx.y;
    int t = threadIdx.x;            // 256: one col each
    if (blockIdx.x == 128) {        // cleanup block: clear membership bits for next replay
        if (r == 0)
            for (int i = t; i < BB; i += 256) g_inb[g_bn[i]] = 0;
        return;
    }
    int c = g_cnt[r];
    for (int e = blockIdx.x; e < c; e += 128) {
        int s = g_ks[r][e], d = g_kd[r][e];
        float coeff = rsqrtf(g_deg[r][s]) * rsqrtf(g_deg[r][d]);
        const float* src = g_xw2 + ((size_t)(r * BB + s)) * OUTD;
        float* dst = out + (size_t)r * BB * OUTD + (size_t)d * OUTD;
        atomicAdd(dst + t, coeff * src[t]);
    }
}

// ---------------- launch ----------------
extern "C" void kernel_launch(void* const* d_in, const int* in_sizes, int n_in,
                              void* d_out, int out_size) {
    const float* feat  = (const float*)d_in[0];
    const float* W1    = (const float*)d_in[1];
    const float* b1    = (const float*)d_in[2];
    const float* W2    = (const float*)d_in[3];
    const float* b2    = (const float*)d_in[4];
    const float* gamma = (const float*)d_in[5];
    const float* beta  = (const float*)d_in[6];
    const void*  ei    = d_in[7];
    const void*  bn    = d_in[8];
    float* out = (float*)d_out;

    k_prep<<<64, 256>>>(bn);
    k_mask<<<dim3((EE / 4 + 255) / 256, RR), 256>>>(ei, bn);
    k_scanmap<<<RR, 1024>>>();
    k_gemm1<<<dim3(BB / 64, HID / 64, RR), 128>>>(feat, W1, b1);
    k_scatter1<<<dim3(128, RR), 256>>>();
    k_gemm2<<<dim3(BB / 64, OUTD / 64, RR), 128>>>(W2, b2, gamma, beta, out);
    k_scatter2<<<dim3(129, RR), 256>>>(out);
}